// round 6
// baseline (speedup 1.0000x reference)
#include <cuda_runtime.h>

#define NB     64
#define NT     1024
#define MAXLAG 256
#define NPOS   16          /* chunks of position-PAIRS, stride 32 positions */
#define NPAIR  (NT/2)      /* 512 float4 per trajectory */

// Scratch (device globals; allocation forbidden). Partials fully overwritten
// each launch. Counters self-reset -> deterministic across graph replays.
__device__ float    g_corr_part[NB][NPOS][MAXLAG];
__device__ float    g_per_traj[NB];
__device__ unsigned g_cnt_traj[NB];
__device__ unsigned g_cnt_final;

// lengths declared int64 in the reference but JAX w/o x64 emits int32.
// Little-endian int64 -> every odd 32-bit word is 0; int32 -> word1 >= 512.
__device__ __forceinline__ int read_len(const int* __restrict__ p, int b)
{
    return (p[1] == 0) ? p[2 * b] : p[b];
}

__device__ __forceinline__ float block_sum_256(float v, float* sbuf)
{
    #pragma unroll
    for (int o = 16; o > 0; o >>= 1)
        v += __shfl_down_sync(0xffffffffu, v, o);
    const int warp = threadIdx.x >> 5;
    if ((threadIdx.x & 31) == 0) sbuf[warp] = v;
    __syncthreads();
    if (threadIdx.x < 8) {
        v = sbuf[threadIdx.x];
        #pragma unroll
        for (int o = 4; o > 0; o >>= 1)
            v += __shfl_down_sync(0xffu, v, o);
        if (threadIdx.x == 0) sbuf[0] = v;
    }
    __syncthreads();
    float r = sbuf[0];
    __syncthreads();
    return r;
}

// ---------------------------------------------------------------------------
// Fused kernel. grid = (NB, NPOS), block = 256 (thread t <-> lag L = t+1).
// Phase 1: partial cross-correlation C[L] = sum_p y[p].y[p+L], p < len-L.
// Phase 2 (last block per b): prefix-scan of |y[p]|^2 + log-fit loss.
// Phase 3 (last finalizer): mean over trajectories.
// ---------------------------------------------------------------------------
__global__ __launch_bounds__(256) void fused_kernel(
    const float* __restrict__ traj,
    const int*   __restrict__ lengths_raw,
    const float* __restrict__ alpha_pred,
    float*       __restrict__ out)
{
    __shared__ __align__(16) float2 y[NT];
    __shared__ float    es[NT + 1];     // exclusive prefix of |y[p]|^2
    __shared__ float    sbuf[8];
    __shared__ unsigned s_flag;

    const int b     = blockIdx.x;
    const int chunk = blockIdx.y;
    const int t     = threadIdx.x;
    const int L     = t + 1;

    // ---- load trajectory into smem (vectorized) ------------------------
    {
        const float4* src = reinterpret_cast<const float4*>(traj + (size_t)b * NT * 2);
        float4* dst = reinterpret_cast<float4*>(y);
        #pragma unroll
        for (int i = t; i < NPAIR; i += 256)
            dst[i] = src[i];
    }
    __syncthreads();

    const int len   = read_len(lengths_raw, b);
    const int bound = len - L;                 // valid positions p in [0,bound)

    // ---- Phase 1: C[L] partial over position pairs (2*chunk + 32k) -----
    const unsigned long long* y64 = reinterpret_cast<const unsigned long long*>(y);
    const ulonglong2*         y128 = reinterpret_cast<const ulonglong2*>(y);

    unsigned long long acc0 = 0ULL, acc1 = 0ULL;   // packed {0.f,0.f}
    int p = 2 * chunk;
    #pragma unroll 4
    for (; p + 1 < bound; p += 32) {
        ulonglong2 s = y128[p >> 1];               // y[p], y[p+1] (broadcast)
        unsigned long long e0 = y64[p + L];
        unsigned long long e1 = y64[p + 1 + L];
        asm("fma.rn.f32x2 %0, %1, %2, %0;" : "+l"(acc0) : "l"(s.x), "l"(e0));
        asm("fma.rn.f32x2 %0, %1, %2, %0;" : "+l"(acc1) : "l"(s.y), "l"(e1));
    }
    if (p < bound) {                               // odd tail position
        unsigned long long s = y64[p];
        unsigned long long e = y64[p + L];
        asm("fma.rn.f32x2 %0, %1, %2, %0;" : "+l"(acc0) : "l"(s), "l"(e));
    }
    float a0x, a0y, a1x, a1y;
    asm("mov.b64 {%0, %1}, %2;" : "=f"(a0x), "=f"(a0y) : "l"(acc0));
    asm("mov.b64 {%0, %1}, %2;" : "=f"(a1x), "=f"(a1y) : "l"(acc1));

    g_corr_part[b][chunk][t] = (a0x + a0y) + (a1x + a1y);

    // ---- elect finalizer block for this trajectory ---------------------
    __threadfence();
    __syncthreads();
    if (t == 0) s_flag = atomicAdd(&g_cnt_traj[b], 1u);
    __syncthreads();
    if (s_flag != NPOS - 1) return;                // uniform per block

    // ---- Phase 2a: exclusive prefix scan of w[p] = |y[p]|^2 ------------
    if (t == 0) g_cnt_traj[b] = 0u;                // reset for next replay

    // each thread handles 4 consecutive positions
    float w0, w1, w2, w3;
    {
        ulonglong2 qa = y128[2 * t];
        ulonglong2 qb = y128[2 * t + 1];
        float x0, y0_, x1, y1_, x2, y2_, x3, y3_;
        asm("mov.b64 {%0, %1}, %2;" : "=f"(x0), "=f"(y0_) : "l"(qa.x));
        asm("mov.b64 {%0, %1}, %2;" : "=f"(x1), "=f"(y1_) : "l"(qa.y));
        asm("mov.b64 {%0, %1}, %2;" : "=f"(x2), "=f"(y2_) : "l"(qb.x));
        asm("mov.b64 {%0, %1}, %2;" : "=f"(x3), "=f"(y3_) : "l"(qb.y));
        w0 = x0 * x0 + y0_ * y0_;
        w1 = x1 * x1 + y1_ * y1_;
        w2 = x2 * x2 + y2_ * y2_;
        w3 = x3 * x3 + y3_ * y3_;
    }
    const float tsum = w0 + w1 + w2 + w3;

    // inclusive warp scan of per-thread sums
    float incl = tsum;
    #pragma unroll
    for (int o = 1; o < 32; o <<= 1) {
        float n = __shfl_up_sync(0xffffffffu, incl, o);
        if ((t & 31) >= o) incl += n;
    }
    if ((t & 31) == 31) sbuf[t >> 5] = incl;       // warp totals
    __syncthreads();
    if (t < 8) {                                    // scan 8 warp totals
        float wv = sbuf[t];
        #pragma unroll
        for (int o = 1; o < 8; o <<= 1) {
            float n = __shfl_up_sync(0xffu, wv, o);
            if (t >= o) wv += n;
        }
        sbuf[t] = wv;                               // inclusive warp prefix
    }
    __syncthreads();
    const int warp = t >> 5;
    float base = (warp ? sbuf[warp - 1] : 0.0f) + (incl - tsum);  // exclusive
    es[4 * t + 0] = base;
    es[4 * t + 1] = base + w0;
    es[4 * t + 2] = base + w0 + w1;
    es[4 * t + 3] = base + w0 + w1 + w2;
    if (t == 255) es[NT] = base + tsum;
    __syncthreads();

    // ---- Phase 2b: per-lag MSD and log-fit loss ------------------------
    float C = 0.0f;
    #pragma unroll
    for (int c = 0; c < NPOS; c++)
        C += g_corr_part[b][c][t];

    const float msd_sum = (es[len] - es[L]) + es[len - L] - 2.0f * C;
    const float count   = fmaxf((float)bound, 1.0f);
    const float msd     = msd_sum / count;

    const float log_msd = logf(msd + 1e-8f);
    const float log_lag = logf((float)L);
    const float alpha   = alpha_pred[b];
    const float mask    = (len > L) ? 1.0f : 0.0f;
    const float resid   = log_msd - alpha * log_lag;

    const float denom     = fmaxf(block_sum_256(mask, sbuf), 1.0f);
    const float intercept = block_sum_256(resid * mask, sbuf) / denom;

    const float err = alpha * log_lag + intercept - log_msd;
    const float per_traj = block_sum_256(err * err * mask, sbuf) / denom;

    // ---- elect mean block ----------------------------------------------
    if (t == 0) {
        g_per_traj[b] = per_traj;
        __threadfence();
        s_flag = atomicAdd(&g_cnt_final, 1u);
    }
    __syncthreads();
    if (s_flag != NB - 1) return;

    // ---- Phase 3: mean over trajectories -------------------------------
    if (t == 0) g_cnt_final = 0u;                  // reset for next replay

    if (t < 64) {
        float v = g_per_traj[t];
        #pragma unroll
        for (int o = 16; o > 0; o >>= 1)
            v += __shfl_down_sync(0xffffffffu, v, o);
        if ((t & 31) == 0) sbuf[t >> 5] = v;
    }
    __syncthreads();
    if (t == 0) out[0] = (sbuf[0] + sbuf[1]) * (1.0f / (float)NB);
}

// ---------------------------------------------------------------------------
extern "C" void kernel_launch(void* const* d_in, const int* in_sizes, int n_in,
                              void* d_out, int out_size)
{
    const float* alpha       = (const float*)d_in[0];   // [64]
    const float* traj        = (const float*)d_in[1];   // [64,1024,2]
    const int*   lengths_raw = (const int*)d_in[2];     // [64] int32 or int64
    float* out = (float*)d_out;

    dim3 grid(NB, NPOS);
    fused_kernel<<<grid, 256>>>(traj, lengths_raw, alpha, out);
}

// round 7
// speedup vs baseline: 1.0022x; 1.0022x over previous
#include <cuda_runtime.h>

#define NB     64
#define NT     1024
#define MAXLAG 256
#define NPOS   16          /* chunks of position-PAIRS, stride 32 positions */
#define NPAIR  (NT/2)      /* 512 float4 per trajectory */

// Scratch (device globals; allocation forbidden). Partials fully overwritten
// each launch. Counters self-reset -> deterministic across graph replays.
__device__ float    g_corr_part[NB][NPOS][MAXLAG];
__device__ float    g_per_traj[NB];
__device__ unsigned g_cnt_traj[NB];
__device__ unsigned g_cnt_final;

// lengths declared int64 in the reference but JAX w/o x64 emits int32.
// Little-endian int64 -> every odd 32-bit word is 0; int32 -> word1 >= 512.
__device__ __forceinline__ int read_len(const int* __restrict__ p, int b)
{
    return (p[1] == 0) ? p[2 * b] : p[b];
}

#define FMA2(acc, s, e) \
    asm("fma.rn.f32x2 %0, %1, %2, %0;" : "+l"(acc) : "l"(s), "l"(e))

__device__ __forceinline__ float block_sum_256(float v, float* sbuf)
{
    #pragma unroll
    for (int o = 16; o > 0; o >>= 1)
        v += __shfl_down_sync(0xffffffffu, v, o);
    const int warp = threadIdx.x >> 5;
    if ((threadIdx.x & 31) == 0) sbuf[warp] = v;
    __syncthreads();
    if (threadIdx.x < 8) {
        v = sbuf[threadIdx.x];
        #pragma unroll
        for (int o = 4; o > 0; o >>= 1)
            v += __shfl_down_sync(0xffu, v, o);
        if (threadIdx.x == 0) sbuf[0] = v;
    }
    __syncthreads();
    float r = sbuf[0];
    __syncthreads();
    return r;
}

// ---------------------------------------------------------------------------
// Fused kernel. grid = (NB, NPOS), block = 256 (thread t <-> lag L = t+1).
// Phase 1: partial cross-correlation C[L] = sum_p y[p].y[p+L], p < len-L.
//   Thread owns position-pairs {2c, 2c+1} (mod 32); hyper-unrolled 4 strides
//   per body (8 positions, 12 imm-offset LDS, 8 FFMA2 on 4 acc chains).
// Phase 2 (last block per b): prefix-scan of |y|^2 + log-fit loss.
// Phase 3 (last finalizer): mean over trajectories.
// ---------------------------------------------------------------------------
__global__ __launch_bounds__(256) void fused_kernel(
    const float* __restrict__ traj,
    const int*   __restrict__ lengths_raw,
    const float* __restrict__ alpha_pred,
    float*       __restrict__ out)
{
    __shared__ __align__(16) float2 y[NT];
    __shared__ float    es[NT + 1];
    __shared__ float    sbuf[8];
    __shared__ unsigned s_flag;

    const int b     = blockIdx.x;
    const int chunk = blockIdx.y;
    const int t     = threadIdx.x;
    const int L     = t + 1;

    // ---- load trajectory into smem (vectorized) ------------------------
    {
        const float4* src = reinterpret_cast<const float4*>(traj + (size_t)b * NT * 2);
        float4* dst = reinterpret_cast<float4*>(y);
        #pragma unroll
        for (int i = t; i < NPAIR; i += 256)
            dst[i] = src[i];
    }
    __syncthreads();

    const int len   = read_len(lengths_raw, b);
    const int bound = len - L;                 // valid positions p in [0,bound)

    // ---- Phase 1: C[L] partials ----------------------------------------
    const unsigned long long* y64  = reinterpret_cast<const unsigned long long*>(y);
    const ulonglong2*         y128 = reinterpret_cast<const ulonglong2*>(y);

    unsigned long long acc0 = 0ULL, acc1 = 0ULL, acc2 = 0ULL, acc3 = 0ULL;

    int p = 2 * chunk;
    {
        // moving base pointers; all loads below use constant offsets
        const ulonglong2*         sp = y128 + chunk;     // p>>1
        const unsigned long long* ep = y64 + p + L;

        // hyper body: positions p..p+1, p+32..33, p+64..65, p+96..97
        for (; p + 97 < bound; p += 128, sp += 64, ep += 128) {
            ulonglong2 s0 = sp[0];
            ulonglong2 s1 = sp[16];
            ulonglong2 s2 = sp[32];
            ulonglong2 s3 = sp[48];
            unsigned long long e0 = ep[0],  e1 = ep[1];
            unsigned long long e2 = ep[32], e3 = ep[33];
            unsigned long long e4 = ep[64], e5 = ep[65];
            unsigned long long e6 = ep[96], e7 = ep[97];
            FMA2(acc0, s0.x, e0); FMA2(acc0, s0.y, e1);
            FMA2(acc1, s1.x, e2); FMA2(acc1, s1.y, e3);
            FMA2(acc2, s2.x, e4); FMA2(acc2, s2.y, e5);
            FMA2(acc3, s3.x, e6); FMA2(acc3, s3.y, e7);
        }
        // remainder pair-groups (up to 3)
        for (; p + 1 < bound; p += 32, sp += 16, ep += 32) {
            ulonglong2 s = sp[0];
            unsigned long long e0 = ep[0], e1 = ep[1];
            FMA2(acc0, s.x, e0);
            FMA2(acc1, s.y, e1);
        }
        // trailing single position
        if (p < bound) {
            unsigned long long s = y64[p];
            unsigned long long e = y64[p + L];
            FMA2(acc2, s, e);
        }
    }

    {
        unsigned long long m01, m23;
        asm("add.rn.f32x2 %0, %1, %2;" : "=l"(m01) : "l"(acc0), "l"(acc1));
        asm("add.rn.f32x2 %0, %1, %2;" : "=l"(m23) : "l"(acc2), "l"(acc3));
        asm("add.rn.f32x2 %0, %1, %2;" : "=l"(m01) : "l"(m01), "l"(m23));
        float cx, cy;
        asm("mov.b64 {%0, %1}, %2;" : "=f"(cx), "=f"(cy) : "l"(m01));
        g_corr_part[b][chunk][t] = cx + cy;
    }

    // ---- elect finalizer block for this trajectory ---------------------
    __threadfence();
    __syncthreads();
    if (t == 0) s_flag = atomicAdd(&g_cnt_traj[b], 1u);
    __syncthreads();
    if (s_flag != NPOS - 1) return;                // uniform per block

    // ---- Phase 2a: exclusive prefix scan of w[p] = |y[p]|^2 ------------
    if (t == 0) g_cnt_traj[b] = 0u;                // reset for next replay

    float w0, w1, w2, w3;
    {
        ulonglong2 qa = y128[2 * t];
        ulonglong2 qb = y128[2 * t + 1];
        float x0, y0_, x1, y1_, x2, y2_, x3, y3_;
        asm("mov.b64 {%0, %1}, %2;" : "=f"(x0), "=f"(y0_) : "l"(qa.x));
        asm("mov.b64 {%0, %1}, %2;" : "=f"(x1), "=f"(y1_) : "l"(qa.y));
        asm("mov.b64 {%0, %1}, %2;" : "=f"(x2), "=f"(y2_) : "l"(qb.x));
        asm("mov.b64 {%0, %1}, %2;" : "=f"(x3), "=f"(y3_) : "l"(qb.y));
        w0 = x0 * x0 + y0_ * y0_;
        w1 = x1 * x1 + y1_ * y1_;
        w2 = x2 * x2 + y2_ * y2_;
        w3 = x3 * x3 + y3_ * y3_;
    }
    const float tsum = w0 + w1 + w2 + w3;

    float incl = tsum;
    #pragma unroll
    for (int o = 1; o < 32; o <<= 1) {
        float n = __shfl_up_sync(0xffffffffu, incl, o);
        if ((t & 31) >= o) incl += n;
    }
    if ((t & 31) == 31) sbuf[t >> 5] = incl;
    __syncthreads();
    if (t < 8) {
        float wv = sbuf[t];
        #pragma unroll
        for (int o = 1; o < 8; o <<= 1) {
            float n = __shfl_up_sync(0xffu, wv, o);
            if (t >= o) wv += n;
        }
        sbuf[t] = wv;
    }
    __syncthreads();
    const int warp = t >> 5;
    float base = (warp ? sbuf[warp - 1] : 0.0f) + (incl - tsum);
    es[4 * t + 0] = base;
    es[4 * t + 1] = base + w0;
    es[4 * t + 2] = base + w0 + w1;
    es[4 * t + 3] = base + w0 + w1 + w2;
    if (t == 255) es[NT] = base + tsum;
    __syncthreads();

    // ---- Phase 2b: per-lag MSD and log-fit loss ------------------------
    float C = 0.0f;
    #pragma unroll
    for (int c = 0; c < NPOS; c++)
        C += g_corr_part[b][c][t];

    const float msd_sum = (es[len] - es[L]) + es[len - L] - 2.0f * C;
    const float count   = fmaxf((float)bound, 1.0f);
    const float msd     = msd_sum / count;

    const float log_msd = logf(msd + 1e-8f);
    const float log_lag = logf((float)L);
    const float alpha   = alpha_pred[b];
    const float mask    = (len > L) ? 1.0f : 0.0f;
    const float resid   = log_msd - alpha * log_lag;

    const float denom     = fmaxf(block_sum_256(mask, sbuf), 1.0f);
    const float intercept = block_sum_256(resid * mask, sbuf) / denom;

    const float err = alpha * log_lag + intercept - log_msd;
    const float per_traj = block_sum_256(err * err * mask, sbuf) / denom;

    // ---- elect mean block ----------------------------------------------
    if (t == 0) {
        g_per_traj[b] = per_traj;
        __threadfence();
        s_flag = atomicAdd(&g_cnt_final, 1u);
    }
    __syncthreads();
    if (s_flag != NB - 1) return;

    // ---- Phase 3: mean over trajectories -------------------------------
    if (t == 0) g_cnt_final = 0u;                  // reset for next replay

    if (t < 64) {
        float v = g_per_traj[t];
        #pragma unroll
        for (int o = 16; o > 0; o >>= 1)
            v += __shfl_down_sync(0xffffffffu, v, o);
        if ((t & 31) == 0) sbuf[t >> 5] = v;
    }
    __syncthreads();
    if (t == 0) out[0] = (sbuf[0] + sbuf[1]) * (1.0f / (float)NB);
}

// ---------------------------------------------------------------------------
extern "C" void kernel_launch(void* const* d_in, const int* in_sizes, int n_in,
                              void* d_out, int out_size)
{
    const float* alpha       = (const float*)d_in[0];   // [64]
    const float* traj        = (const float*)d_in[1];   // [64,1024,2]
    const int*   lengths_raw = (const int*)d_in[2];     // [64] int32 or int64
    float* out = (float*)d_out;

    dim3 grid(NB, NPOS);
    fused_kernel<<<grid, 256>>>(traj, lengths_raw, alpha, out);
}